// round 13
// baseline (speedup 1.0000x reference)
#include <cuda_runtime.h>
#include <cuda_bf16.h>
#include <mma.h>
#include <cstdint>

using namespace nvcuda;

#define TBG   512
#define TIN   256
#define MROWS 2048      // B*N = 32*64

#define BM    32        // m rows per CTA
#define BI    64        // i cols per CTA
#define LDW   520       // padded bf16 leading dim (1040B rows, conflict-free)
#define LDP   68        // padded f32 leading dim for partial tiles

// smem layout (dynamic):
//   As  : BM x LDW bf16                    [0, 33280)
//   Ws  : BI x LDW bf16                    [33280, 99840)
//   q   : 512 float4 (u, e^-bu, e^+bu, 0)  [99840, 108032)
//   tin : 64 float                          [108032, 108288)
//   Ps[3]: 3 x (BM x LDP f32) k-split partials, ALIAS over As (dead by then)
#define AS_BYTES   (BM * LDW * 2)
#define WS_OFF     AS_BYTES
#define WS_BYTES   (BI * LDW * 2)
#define Q_OFF      (WS_OFF + WS_BYTES)
#define TIN_OFF    (Q_OFF + TBG * 16)
#define SMEM_TOTAL (TIN_OFF + BI * 4)
#define PS_BYTES   (BM * LDP * 4)

__global__ void __launch_bounds__(256, 2)
fused_kernel(const float* __restrict__ surv,
             const float* __restrict__ time_bg,
             const float* __restrict__ time_in,
             const float* __restrict__ bandwidth,
             float* __restrict__ C) {
    extern __shared__ char smem[];
    __nv_bfloat16* As  = reinterpret_cast<__nv_bfloat16*>(smem);
    __nv_bfloat16* Ws  = reinterpret_cast<__nv_bfloat16*>(smem + WS_OFF);
    float4*        q   = reinterpret_cast<float4*>(smem + Q_OFF);
    float*         tin = reinterpret_cast<float*>(smem + TIN_OFF);

    const int tid = threadIdx.x;
    const int wid = tid >> 5;
    const int lid = tid & 31;

    const int i0 = blockIdx.x * BI;   // output col block (T_in)
    const int m0 = blockIdx.y * BM;   // output row block (B*N)

    const float b = fmaxf(bandwidth[0], 1e-6f);

    // ---- 1. prefetch time_in block + exp table ----
    if (tid < BI) tin[tid] = time_in[i0 + tid];
    {
        const float u0 = time_bg[tid];
        const float u1 = time_bg[tid + 256];
        q[tid]       = make_float4(u0, __expf(-b * u0), __expf(b * u0), 0.0f);
        q[tid + 256] = make_float4(u1, __expf(-b * u1), __expf(b * u1), 0.0f);
    }

    // ---- 2. A tile [BM x 512] fp32 -> bf16 smem (16 float4 / thread) ----
    {
        const float* Ag = surv + (size_t)m0 * TBG;
        #pragma unroll
        for (int it = 0; it < 16; it++) {
            const int idx = it * 256 + tid;    // 4096 float4 total
            const int r   = idx >> 7;          // 0..31
            const int c4  = idx & 127;
            const float4 v = *reinterpret_cast<const float4*>(Ag + (size_t)r * TBG + c4 * 4);
            __nv_bfloat162 p0 = __floats2bfloat162_rn(v.x, v.y);
            __nv_bfloat162 p1 = __floats2bfloat162_rn(v.z, v.w);
            uint2 o;
            o.x = *reinterpret_cast<unsigned int*>(&p0);
            o.y = *reinterpret_cast<unsigned int*>(&p1);
            *reinterpret_cast<uint2*>(&As[r * LDW + c4 * 4]) = o;
        }
    }
    __syncthreads();   // q, tin, As ready

    // ---- 3. softmin weights, factorized (one exp per i): 8 i's / warp ----
    // raw_t = (u_t >= v) ? e^{-b u_t} : e^{+b u_t} * e^{-2 b v}
    {
        #pragma unroll 1
        for (int ii = 0; ii < 8; ii++) {
            const int i   = wid * 8 + ii;            // local i 0..63
            const float v = tin[i];
            const float g = __expf(-2.0f * b * v);

            float w[16];
            float sm = 0.0f;
            #pragma unroll
            for (int j = 0; j < 16; j++) {
                const float4 qq = q[j * 32 + lid];
                const float raw = (qq.x >= v) ? qq.y : qq.z * g;
                w[j] = raw;
                sm += raw;
            }
            #pragma unroll
            for (int o = 16; o > 0; o >>= 1)
                sm += __shfl_xor_sync(0xffffffffu, sm, o);

            const float inv = __fdividef(1.0f, sm);
            #pragma unroll
            for (int j = 0; j < 16; j++)
                Ws[i * LDW + j * 32 + lid] = __float2bfloat16(w[j] * inv);
        }
    }
    __syncthreads();

    // ---- 4. MMA, k-split x4: warp wk = wid>>1 owns k [wk*128,(wk+1)*128)
    //         per k-quarter: 2 warps, warp tile 32m x 32i (2x2 frags)
    const int wk = wid >> 1;         // 0..3
    const int wi = wid & 1;          // 0..1

    wmma::fragment<wmma::accumulator, 16, 16, 16, float> acc[2][2];
    #pragma unroll
    for (int fm = 0; fm < 2; fm++)
        #pragma unroll
        for (int fi = 0; fi < 2; fi++)
            wmma::fill_fragment(acc[fm][fi], 0.0f);

    {
        const __nv_bfloat16* a_base = &As[wk * 128];
        const __nv_bfloat16* b_base = &Ws[(wi * 32) * LDW + wk * 128];

        #pragma unroll 4
        for (int kk = 0; kk < 128; kk += 16) {
            wmma::fragment<wmma::matrix_a, 16, 16, 16, __nv_bfloat16, wmma::row_major> af[2];
            wmma::fragment<wmma::matrix_b, 16, 16, 16, __nv_bfloat16, wmma::col_major> bf[2];
            wmma::load_matrix_sync(af[0], a_base + kk, LDW);
            wmma::load_matrix_sync(af[1], a_base + 16 * LDW + kk, LDW);
            wmma::load_matrix_sync(bf[0], b_base + kk, LDW);
            wmma::load_matrix_sync(bf[1], b_base + 16 * LDW + kk, LDW);
            #pragma unroll
            for (int fm = 0; fm < 2; fm++)
                #pragma unroll
                for (int fi = 0; fi < 2; fi++)
                    wmma::mma_sync(acc[fm][fi], af[fm], bf[fi], acc[fm][fi]);
        }
    }

    // ---- 5. reduce 4 k-quarters (Ps aliases As after this barrier) ----
    __syncthreads();    // all MMA smem reads done
    if (wk > 0) {
        float* Ps = reinterpret_cast<float*>(smem + (wk - 1) * PS_BYTES);
        #pragma unroll
        for (int fm = 0; fm < 2; fm++)
            #pragma unroll
            for (int fi = 0; fi < 2; fi++)
                wmma::store_matrix_sync(&Ps[(fm * 16) * LDP + wi * 32 + fi * 16],
                                        acc[fm][fi], LDP, wmma::mem_row_major);
    }
    __syncthreads();
    if (wk == 0) {
        wmma::fragment<wmma::accumulator, 16, 16, 16, float> pf;
        #pragma unroll
        for (int fm = 0; fm < 2; fm++)
            #pragma unroll
            for (int fi = 0; fi < 2; fi++) {
                #pragma unroll
                for (int s = 0; s < 3; s++) {
                    const float* Ps = reinterpret_cast<const float*>(smem + s * PS_BYTES);
                    wmma::load_matrix_sync(pf, &Ps[(fm * 16) * LDP + wi * 32 + fi * 16],
                                           LDP, wmma::mem_row_major);
                    #pragma unroll
                    for (int t = 0; t < pf.num_elements; t++)
                        acc[fm][fi].x[t] += pf.x[t];
                }
                float* cp = C + (size_t)(m0 + fm * 16) * TIN + i0 + wi * 32 + fi * 16;
                wmma::store_matrix_sync(cp, acc[fm][fi], TIN, wmma::mem_row_major);
            }
    }
}

// ===========================================================================
extern "C" void kernel_launch(void* const* d_in, const int* in_sizes, int n_in,
                              void* d_out, int out_size) {
    const float* surv      = (const float*)d_in[0];
    const float* time_bg   = (const float*)d_in[1];
    const float* time_in   = (const float*)d_in[2];
    const float* bandwidth = (const float*)d_in[3];
    float*       out       = (float*)d_out;

    static bool attr_done = false;
    if (!attr_done) {
        cudaFuncSetAttribute(fused_kernel,
                             cudaFuncAttributeMaxDynamicSharedMemorySize, SMEM_TOTAL);
        attr_done = true;
    }

    dim3 grid(TIN / BI, MROWS / BM);   // (4, 64) = 256 CTAs, 2 per SM, 1 wave
    fused_kernel<<<grid, 256, SMEM_TOTAL>>>(surv, time_bg, time_in, bandwidth, out);
}

// round 14
// speedup vs baseline: 1.1941x; 1.1941x over previous
#include <cuda_runtime.h>
#include <cuda_bf16.h>
#include <mma.h>
#include <cstdint>

using namespace nvcuda;

#define TBG   512
#define TIN   256
#define MROWS 2048      // B*N = 32*64

#define BM    64
#define BI    64
#define LDW   520       // padded bf16 leading dim (1040B rows, conflict-free)
#define LDP   68        // padded f32 leading dim for partial tiles

// smem layout (dynamic):
//   As  : BM x LDW bf16                    [0, 66560)
//   Ws  : BI x LDW bf16                    [66560, 133120)
//   q   : 512 float4 (u, e^-bu, e^+bu, 0)  [133120, 141312)
//   tin : 64 float                         [141312, 141568)
//   Ps[3]: 3 x (BM x LDP f32) k-split partials, ALIAS over As (dead by then)
#define AS_BYTES   (BM * LDW * 2)
#define WS_OFF     AS_BYTES
#define WS_BYTES   (BI * LDW * 2)
#define Q_OFF      (WS_OFF + WS_BYTES)
#define TIN_OFF    (Q_OFF + TBG * 16)
#define SMEM_TOTAL (TIN_OFF + BI * 4)
#define PS_BYTES   (BM * LDP * 4)       // 17408; 3x = 52224 < AS_BYTES

__global__ void __launch_bounds__(512, 1)
fused_kernel(const float* __restrict__ surv,
             const float* __restrict__ time_bg,
             const float* __restrict__ time_in,
             const float* __restrict__ bandwidth,
             float* __restrict__ C) {
    extern __shared__ char smem[];
    __nv_bfloat16* As  = reinterpret_cast<__nv_bfloat16*>(smem);
    __nv_bfloat16* Ws  = reinterpret_cast<__nv_bfloat16*>(smem + WS_OFF);
    float4*        q   = reinterpret_cast<float4*>(smem + Q_OFF);
    float*         tin = reinterpret_cast<float*>(smem + TIN_OFF);

    const int tid = threadIdx.x;
    const int wid = tid >> 5;
    const int lid = tid & 31;

    const int i0 = blockIdx.x * BI;   // output col block (T_in)
    const int m0 = blockIdx.y * BM;   // output row block (B*N)

    const float b = fmaxf(bandwidth[0], 1e-6f);

    // ---- 1. prefetch time_in block + exp table (one t per thread) ----
    if (tid < BI) tin[tid] = time_in[i0 + tid];
    {
        const float u = time_bg[tid];
        q[tid] = make_float4(u, __expf(-b * u), __expf(b * u), 0.0f);
    }

    // ---- 2. A tile [BM x 512] fp32 -> bf16 smem (16 float4 / thread) ----
    {
        const float* Ag = surv + (size_t)m0 * TBG;
        #pragma unroll
        for (int it = 0; it < 16; it++) {
            const int idx = it * 512 + tid;    // 8192 float4 total
            const int r   = idx >> 7;          // 0..63
            const int c4  = idx & 127;
            const float4 v = *reinterpret_cast<const float4*>(Ag + (size_t)r * TBG + c4 * 4);
            __nv_bfloat162 p0 = __floats2bfloat162_rn(v.x, v.y);
            __nv_bfloat162 p1 = __floats2bfloat162_rn(v.z, v.w);
            uint2 o;
            o.x = *reinterpret_cast<unsigned int*>(&p0);
            o.y = *reinterpret_cast<unsigned int*>(&p1);
            *reinterpret_cast<uint2*>(&As[r * LDW + c4 * 4]) = o;
        }
    }
    __syncthreads();   // q, tin, As ready

    // ---- 3. softmin weights, factorized (one exp per i): 4 i's / warp ----
    // raw_t = (u_t >= v) ? e^{-b u_t} : e^{+b u_t} * e^{-2 b v}
    {
        #pragma unroll 1
        for (int ii = 0; ii < 4; ii++) {
            const int i   = wid * 4 + ii;            // local i 0..63
            const float v = tin[i];
            const float g = __expf(-2.0f * b * v);

            float w[16];
            float sm = 0.0f;
            #pragma unroll
            for (int j = 0; j < 16; j++) {
                const float4 qq = q[j * 32 + lid];
                const float raw = (qq.x >= v) ? qq.y : qq.z * g;
                w[j] = raw;
                sm += raw;
            }
            #pragma unroll
            for (int o = 16; o > 0; o >>= 1)
                sm += __shfl_xor_sync(0xffffffffu, sm, o);

            const float inv = __fdividef(1.0f, sm);
            #pragma unroll
            for (int j = 0; j < 16; j++)
                Ws[i * LDW + j * 32 + lid] = __float2bfloat16(w[j] * inv);
        }
    }
    __syncthreads();

    // ---- 4. MMA, k-split x4: warp group wk = wid>>2 owns k [wk*128, +128)
    //         per quarter: 4 warps as 2m x 2i, warp tile 32m x 32i (2x2 frags)
    const int wk = wid >> 2;         // 0..3
    const int w4 = wid & 3;
    const int wm = w4 >> 1;          // 0..1
    const int wi = w4 & 1;           // 0..1

    wmma::fragment<wmma::accumulator, 16, 16, 16, float> acc[2][2];
    #pragma unroll
    for (int fm = 0; fm < 2; fm++)
        #pragma unroll
        for (int fi = 0; fi < 2; fi++)
            wmma::fill_fragment(acc[fm][fi], 0.0f);

    {
        const __nv_bfloat16* a_base = &As[(wm * 32) * LDW + wk * 128];
        const __nv_bfloat16* b_base = &Ws[(wi * 32) * LDW + wk * 128];

        #pragma unroll 8
        for (int kk = 0; kk < 128; kk += 16) {
            wmma::fragment<wmma::matrix_a, 16, 16, 16, __nv_bfloat16, wmma::row_major> af[2];
            wmma::fragment<wmma::matrix_b, 16, 16, 16, __nv_bfloat16, wmma::col_major> bf[2];
            wmma::load_matrix_sync(af[0], a_base + kk, LDW);
            wmma::load_matrix_sync(af[1], a_base + 16 * LDW + kk, LDW);
            wmma::load_matrix_sync(bf[0], b_base + kk, LDW);
            wmma::load_matrix_sync(bf[1], b_base + 16 * LDW + kk, LDW);
            #pragma unroll
            for (int fm = 0; fm < 2; fm++)
                #pragma unroll
                for (int fi = 0; fi < 2; fi++)
                    wmma::mma_sync(acc[fm][fi], af[fm], bf[fi], acc[fm][fi]);
        }
    }

    // ---- 5. reduce 4 k-quarters (Ps aliases As after this barrier) ----
    __syncthreads();    // all MMA smem reads done
    if (wk > 0) {
        float* Ps = reinterpret_cast<float*>(smem + (wk - 1) * PS_BYTES);
        #pragma unroll
        for (int fm = 0; fm < 2; fm++)
            #pragma unroll
            for (int fi = 0; fi < 2; fi++)
                wmma::store_matrix_sync(
                    &Ps[(wm * 32 + fm * 16) * LDP + wi * 32 + fi * 16],
                    acc[fm][fi], LDP, wmma::mem_row_major);
    }
    __syncthreads();
    if (wk == 0) {
        wmma::fragment<wmma::accumulator, 16, 16, 16, float> pf;
        #pragma unroll
        for (int fm = 0; fm < 2; fm++)
            #pragma unroll
            for (int fi = 0; fi < 2; fi++) {
                #pragma unroll
                for (int s = 0; s < 3; s++) {
                    const float* Ps = reinterpret_cast<const float*>(smem + s * PS_BYTES);
                    wmma::load_matrix_sync(
                        pf, &Ps[(wm * 32 + fm * 16) * LDP + wi * 32 + fi * 16],
                        LDP, wmma::mem_row_major);
                    #pragma unroll
                    for (int t = 0; t < pf.num_elements; t++)
                        acc[fm][fi].x[t] += pf.x[t];
                }
                float* cp = C + (size_t)(m0 + wm * 32 + fm * 16) * TIN
                              + i0 + wi * 32 + fi * 16;
                wmma::store_matrix_sync(cp, acc[fm][fi], TIN, wmma::mem_row_major);
            }
    }
}

// ===========================================================================
extern "C" void kernel_launch(void* const* d_in, const int* in_sizes, int n_in,
                              void* d_out, int out_size) {
    const float* surv      = (const float*)d_in[0];
    const float* time_bg   = (const float*)d_in[1];
    const float* time_in   = (const float*)d_in[2];
    const float* bandwidth = (const float*)d_in[3];
    float*       out       = (float*)d_out;

    static bool attr_done = false;
    if (!attr_done) {
        cudaFuncSetAttribute(fused_kernel,
                             cudaFuncAttributeMaxDynamicSharedMemorySize, SMEM_TOTAL);
        attr_done = true;
    }

    dim3 grid(TIN / BI, MROWS / BM);   // (4, 32) = 128 CTAs, 1 wave
    fused_kernel<<<grid, 512, SMEM_TOTAL>>>(surv, time_bg, time_in, bandwidth, out);
}